// round 13
// baseline (speedup 1.0000x reference)
#include <cuda_runtime.h>
#include <cuda_bf16.h>
#include <cstdint>

// ForceGrid (final): NGP deposit of 10M weighted particles into a 256^3 grid.
// Index path replicates XLA bit-exactly: fi5 = RN(RN(RN(x+10) * 12.75f) + 0.5f)
// (reciprocal-mul, three separately-rounded ops), trunc, bounds-check, red.add.
// Perf: grid zeroed+pinned in L2 via evict_last policy stores; reductions carry
// the same evict_last cache hint -> zero random DRAM sector fetches. Deposit is
// a persistent grid-stride loop, double-buffered LDG.128 quads (best measured).
// Structural floor: L1tex REDG wavefront serialization (~2 cyc x 51.4k lanes/SM).

#define GRID_N 256

__device__ __forceinline__ uint64_t make_evict_last_policy() {
    uint64_t pol;
    asm volatile("createpolicy.fractional.L2::evict_last.b64 %0, 1.0;" : "=l"(pol));
    return pol;
}

__device__ __forceinline__ void deposit_one(float x, float y, float z, float w,
                                            float* __restrict__ grid,
                                            uint64_t pol) {
    const float R = 12.75f;  // RN(1 / RN(20/255)) == 12.75 exactly
    float fx = __fadd_rn(__fmul_rn(__fadd_rn(x, 10.0f), R), 0.5f);
    float fy = __fadd_rn(__fmul_rn(__fadd_rn(y, 10.0f), R), 0.5f);
    float fz = __fadd_rn(__fmul_rn(__fadd_rn(z, 10.0f), R), 0.5f);
    int ix = (int)fx;   // trunc toward zero == astype(int32)
    int iy = (int)fy;
    int iz = (int)fz;
    if (((unsigned)ix < GRID_N) & ((unsigned)iy < GRID_N) & ((unsigned)iz < GRID_N)) {
        int flat = (ix * GRID_N + iy) * GRID_N + iz;
        // Reduction with L2 evict_last cache hint: keeps grid lines resident.
        asm volatile("red.global.L2::cache_hint.add.f32 [%0], %1, %2;"
                     :: "l"(grid + flat), "f"(w), "l"(pol) : "memory");
    }
}

// Zero the grid with 256-bit evict_last-policy stores: lines enter L2
// dirty + pinned so deposit-phase atomics never fetch grid sectors from DRAM.
__global__ void __launch_bounds__(256)
forcegrid_zero_kernel(float* __restrict__ grid, int n8) {
    int i = blockIdx.x * blockDim.x + threadIdx.x;
    int stride = gridDim.x * blockDim.x;
    const float z = 0.0f;
    const uint64_t pol = make_evict_last_policy();
    for (; i < n8; i += stride) {
        asm volatile(
            "st.global.L2::cache_hint.v8.f32 [%0], {%1,%2,%3,%4,%5,%6,%7,%8}, %9;"
            :: "l"(grid + 8 * (size_t)i),
               "f"(z), "f"(z), "f"(z), "f"(z), "f"(z), "f"(z), "f"(z), "f"(z),
               "l"(pol)
            : "memory");
    }
}

__global__ void __launch_bounds__(256)
forcegrid_deposit_kernel(const float4* __restrict__ pos4,
                         const float4* __restrict__ w4,
                         const float*  __restrict__ pos_scalar,
                         const float*  __restrict__ w_scalar,
                         float* __restrict__ grid,
                         int n_particles) {
    const int nq = n_particles >> 2;                 // full quads
    const int stride = gridDim.x * blockDim.x;
    int q = blockIdx.x * blockDim.x + threadIdx.x;
    const uint64_t pol = make_evict_last_policy();

    // Software pipeline: cur regs hold quad q, next loads issue before deposits.
    float4 a, b, c, w;
    bool have = (q < nq);
    if (have) {
        a = __ldcs(&pos4[3 * q + 0]);
        b = __ldcs(&pos4[3 * q + 1]);
        c = __ldcs(&pos4[3 * q + 2]);
        w = __ldcs(&w4[q]);
    }
    while (have) {
        const int qn = q + stride;
        const bool haven = (qn < nq);
        float4 an, bn, cn, wn;
        if (haven) {                                  // prefetch next quad
            an = __ldcs(&pos4[3 * qn + 0]);
            bn = __ldcs(&pos4[3 * qn + 1]);
            cn = __ldcs(&pos4[3 * qn + 2]);
            wn = __ldcs(&w4[qn]);
        }
        deposit_one(a.x, a.y, a.z, w.x, grid, pol);
        deposit_one(a.w, b.x, b.y, w.y, grid, pol);
        deposit_one(b.z, b.w, c.x, w.z, grid, pol);
        deposit_one(c.y, c.z, c.w, w.w, grid, pol);
        a = an; b = bn; c = cn; w = wn;               // rotate buffers
        q = qn; have = haven;
    }

    // tail (n_particles % 4 != 0) — single thread, scalar path
    if (blockIdx.x == 0 && threadIdx.x == 0) {
        for (int p = nq * 4; p < n_particles; p++) {
            deposit_one(pos_scalar[3 * p + 0], pos_scalar[3 * p + 1],
                        pos_scalar[3 * p + 2], w_scalar[p], grid, pol);
        }
    }
}

extern "C" void kernel_launch(void* const* d_in, const int* in_sizes, int n_in,
                              void* d_out, int out_size) {
    const float* positions = (const float*)d_in[0];   // [N,3] f32
    const float* weights   = (const float*)d_in[1];   // [N]   f32
    float* grid = (float*)d_out;                      // 256^3 f32

    int n_particles = in_sizes[1];                    // N from weights

    int threads = 256;

    // Zero + L2-pin the grid (out_size = 256^3, divisible by 8).
    int n8 = out_size / 8;
    int zblocks = 148 * 4;
    forcegrid_zero_kernel<<<zblocks, threads, 0, 0>>>(grid, n8);

    // Persistent deposit with grid-stride double-buffer (best measured config).
    int blocks = 148 * 8;
    forcegrid_deposit_kernel<<<blocks, threads, 0, 0>>>(
        (const float4*)positions, (const float4*)weights,
        positions, weights, grid, n_particles);
}

// round 14
// speedup vs baseline: 1.0569x; 1.0569x over previous
#include <cuda_runtime.h>
#include <cuda_bf16.h>
#include <cstdint>

// ForceGrid (converged): NGP deposit of 10M weighted particles into a 256^3 grid.
// Index path replicates XLA bit-exactly: fi5 = RN(RN(RN(x+10) * 12.75f) + 0.5f)
// (reciprocal-mul, three separately-rounded ops), trunc, bounds-check, red.add.
// Perf: grid zeroed+pinned in L2 via evict_last policy stores; reductions carry
// the same evict_last cache hint -> zero random DRAM sector fetches. Deposit is
// a persistent grid-stride loop, double-buffered LDG.128 quads.
// Structural floor: L1tex REDG wavefront serialization (~2 cyc x 51.4k lanes/SM
// = ~82% of the deposit window). Run-to-run variance measured at +/-3-4us.

#define GRID_N 256

__device__ __forceinline__ uint64_t make_evict_last_policy() {
    uint64_t pol;
    asm volatile("createpolicy.fractional.L2::evict_last.b64 %0, 1.0;" : "=l"(pol));
    return pol;
}

__device__ __forceinline__ void deposit_one(float x, float y, float z, float w,
                                            float* __restrict__ grid,
                                            uint64_t pol) {
    const float R = 12.75f;  // RN(1 / RN(20/255)) == 12.75 exactly
    float fx = __fadd_rn(__fmul_rn(__fadd_rn(x, 10.0f), R), 0.5f);
    float fy = __fadd_rn(__fmul_rn(__fadd_rn(y, 10.0f), R), 0.5f);
    float fz = __fadd_rn(__fmul_rn(__fadd_rn(z, 10.0f), R), 0.5f);
    int ix = (int)fx;   // trunc toward zero == astype(int32)
    int iy = (int)fy;
    int iz = (int)fz;
    if (((unsigned)ix < GRID_N) & ((unsigned)iy < GRID_N) & ((unsigned)iz < GRID_N)) {
        int flat = (ix * GRID_N + iy) * GRID_N + iz;
        // Reduction with L2 evict_last cache hint: keeps grid lines resident.
        asm volatile("red.global.L2::cache_hint.add.f32 [%0], %1, %2;"
                     :: "l"(grid + flat), "f"(w), "l"(pol) : "memory");
    }
}

// Zero the grid with 256-bit evict_last-policy stores: lines enter L2
// dirty + pinned so deposit-phase atomics never fetch grid sectors from DRAM.
__global__ void __launch_bounds__(256)
forcegrid_zero_kernel(float* __restrict__ grid, int n8) {
    int i = blockIdx.x * blockDim.x + threadIdx.x;
    int stride = gridDim.x * blockDim.x;
    const float z = 0.0f;
    const uint64_t pol = make_evict_last_policy();
    for (; i < n8; i += stride) {
        asm volatile(
            "st.global.L2::cache_hint.v8.f32 [%0], {%1,%2,%3,%4,%5,%6,%7,%8}, %9;"
            :: "l"(grid + 8 * (size_t)i),
               "f"(z), "f"(z), "f"(z), "f"(z), "f"(z), "f"(z), "f"(z), "f"(z),
               "l"(pol)
            : "memory");
    }
}

__global__ void __launch_bounds__(256)
forcegrid_deposit_kernel(const float4* __restrict__ pos4,
                         const float4* __restrict__ w4,
                         const float*  __restrict__ pos_scalar,
                         const float*  __restrict__ w_scalar,
                         float* __restrict__ grid,
                         int n_particles) {
    const int nq = n_particles >> 2;                 // full quads
    const int stride = gridDim.x * blockDim.x;
    int q = blockIdx.x * blockDim.x + threadIdx.x;
    const uint64_t pol = make_evict_last_policy();

    // Software pipeline: cur regs hold quad q, next loads issue before deposits.
    float4 a, b, c, w;
    bool have = (q < nq);
    if (have) {
        a = __ldcs(&pos4[3 * q + 0]);
        b = __ldcs(&pos4[3 * q + 1]);
        c = __ldcs(&pos4[3 * q + 2]);
        w = __ldcs(&w4[q]);
    }
    while (have) {
        const int qn = q + stride;
        const bool haven = (qn < nq);
        float4 an, bn, cn, wn;
        if (haven) {                                  // prefetch next quad
            an = __ldcs(&pos4[3 * qn + 0]);
            bn = __ldcs(&pos4[3 * qn + 1]);
            cn = __ldcs(&pos4[3 * qn + 2]);
            wn = __ldcs(&w4[qn]);
        }
        deposit_one(a.x, a.y, a.z, w.x, grid, pol);
        deposit_one(a.w, b.x, b.y, w.y, grid, pol);
        deposit_one(b.z, b.w, c.x, w.z, grid, pol);
        deposit_one(c.y, c.z, c.w, w.w, grid, pol);
        a = an; b = bn; c = cn; w = wn;               // rotate buffers
        q = qn; have = haven;
    }

    // tail (n_particles % 4 != 0) — single thread, scalar path
    if (blockIdx.x == 0 && threadIdx.x == 0) {
        for (int p = nq * 4; p < n_particles; p++) {
            deposit_one(pos_scalar[3 * p + 0], pos_scalar[3 * p + 1],
                        pos_scalar[3 * p + 2], w_scalar[p], grid, pol);
        }
    }
}

extern "C" void kernel_launch(void* const* d_in, const int* in_sizes, int n_in,
                              void* d_out, int out_size) {
    const float* positions = (const float*)d_in[0];   // [N,3] f32
    const float* weights   = (const float*)d_in[1];   // [N]   f32
    float* grid = (float*)d_out;                      // 256^3 f32

    int n_particles = in_sizes[1];                    // N from weights

    int threads = 256;

    // Zero + L2-pin the grid (out_size = 256^3, divisible by 8).
    int n8 = out_size / 8;
    int zblocks = 148 * 4;
    forcegrid_zero_kernel<<<zblocks, threads, 0, 0>>>(grid, n8);

    // Persistent deposit with grid-stride double-buffer (best measured config).
    int blocks = 148 * 8;
    forcegrid_deposit_kernel<<<blocks, threads, 0, 0>>>(
        (const float4*)positions, (const float4*)weights,
        positions, weights, grid, n_particles);
}

// round 15
// speedup vs baseline: 1.0580x; 1.0010x over previous
#include <cuda_runtime.h>
#include <cuda_bf16.h>
#include <cstdint>

// ForceGrid (converged): NGP deposit of 10M weighted particles into a 256^3 grid.
// Index path replicates XLA bit-exactly: fi5 = RN(RN(RN(x+10) * 12.75f) + 0.5f)
// (reciprocal-mul, three separately-rounded ops), trunc, bounds-check, red.add.
// Perf: grid zeroed+pinned in L2 via evict_last policy stores; reductions carry
// the same evict_last cache hint -> zero random DRAM sector fetches. Deposit is
// a persistent grid-stride loop, double-buffered LDG.128 quads.
// Structural floor: L1tex REDG wavefront serialization (~2 cyc x 51.4k lanes/SM
// = ~82% of the deposit window). Run-to-run variance measured at +/-3-4us.

#define GRID_N 256

__device__ __forceinline__ uint64_t make_evict_last_policy() {
    uint64_t pol;
    asm volatile("createpolicy.fractional.L2::evict_last.b64 %0, 1.0;" : "=l"(pol));
    return pol;
}

__device__ __forceinline__ void deposit_one(float x, float y, float z, float w,
                                            float* __restrict__ grid,
                                            uint64_t pol) {
    const float R = 12.75f;  // RN(1 / RN(20/255)) == 12.75 exactly
    float fx = __fadd_rn(__fmul_rn(__fadd_rn(x, 10.0f), R), 0.5f);
    float fy = __fadd_rn(__fmul_rn(__fadd_rn(y, 10.0f), R), 0.5f);
    float fz = __fadd_rn(__fmul_rn(__fadd_rn(z, 10.0f), R), 0.5f);
    int ix = (int)fx;   // trunc toward zero == astype(int32)
    int iy = (int)fy;
    int iz = (int)fz;
    if (((unsigned)ix < GRID_N) & ((unsigned)iy < GRID_N) & ((unsigned)iz < GRID_N)) {
        int flat = (ix * GRID_N + iy) * GRID_N + iz;
        // Reduction with L2 evict_last cache hint: keeps grid lines resident.
        asm volatile("red.global.L2::cache_hint.add.f32 [%0], %1, %2;"
                     :: "l"(grid + flat), "f"(w), "l"(pol) : "memory");
    }
}

// Zero the grid with 256-bit evict_last-policy stores: lines enter L2
// dirty + pinned so deposit-phase atomics never fetch grid sectors from DRAM.
__global__ void __launch_bounds__(256)
forcegrid_zero_kernel(float* __restrict__ grid, int n8) {
    int i = blockIdx.x * blockDim.x + threadIdx.x;
    int stride = gridDim.x * blockDim.x;
    const float z = 0.0f;
    const uint64_t pol = make_evict_last_policy();
    for (; i < n8; i += stride) {
        asm volatile(
            "st.global.L2::cache_hint.v8.f32 [%0], {%1,%2,%3,%4,%5,%6,%7,%8}, %9;"
            :: "l"(grid + 8 * (size_t)i),
               "f"(z), "f"(z), "f"(z), "f"(z), "f"(z), "f"(z), "f"(z), "f"(z),
               "l"(pol)
            : "memory");
    }
}

__global__ void __launch_bounds__(256)
forcegrid_deposit_kernel(const float4* __restrict__ pos4,
                         const float4* __restrict__ w4,
                         const float*  __restrict__ pos_scalar,
                         const float*  __restrict__ w_scalar,
                         float* __restrict__ grid,
                         int n_particles) {
    const int nq = n_particles >> 2;                 // full quads
    const int stride = gridDim.x * blockDim.x;
    int q = blockIdx.x * blockDim.x + threadIdx.x;
    const uint64_t pol = make_evict_last_policy();

    // Software pipeline: cur regs hold quad q, next loads issue before deposits.
    float4 a, b, c, w;
    bool have = (q < nq);
    if (have) {
        a = __ldcs(&pos4[3 * q + 0]);
        b = __ldcs(&pos4[3 * q + 1]);
        c = __ldcs(&pos4[3 * q + 2]);
        w = __ldcs(&w4[q]);
    }
    while (have) {
        const int qn = q + stride;
        const bool haven = (qn < nq);
        float4 an, bn, cn, wn;
        if (haven) {                                  // prefetch next quad
            an = __ldcs(&pos4[3 * qn + 0]);
            bn = __ldcs(&pos4[3 * qn + 1]);
            cn = __ldcs(&pos4[3 * qn + 2]);
            wn = __ldcs(&w4[qn]);
        }
        deposit_one(a.x, a.y, a.z, w.x, grid, pol);
        deposit_one(a.w, b.x, b.y, w.y, grid, pol);
        deposit_one(b.z, b.w, c.x, w.z, grid, pol);
        deposit_one(c.y, c.z, c.w, w.w, grid, pol);
        a = an; b = bn; c = cn; w = wn;               // rotate buffers
        q = qn; have = haven;
    }

    // tail (n_particles % 4 != 0) — single thread, scalar path
    if (blockIdx.x == 0 && threadIdx.x == 0) {
        for (int p = nq * 4; p < n_particles; p++) {
            deposit_one(pos_scalar[3 * p + 0], pos_scalar[3 * p + 1],
                        pos_scalar[3 * p + 2], w_scalar[p], grid, pol);
        }
    }
}

extern "C" void kernel_launch(void* const* d_in, const int* in_sizes, int n_in,
                              void* d_out, int out_size) {
    const float* positions = (const float*)d_in[0];   // [N,3] f32
    const float* weights   = (const float*)d_in[1];   // [N]   f32
    float* grid = (float*)d_out;                      // 256^3 f32

    int n_particles = in_sizes[1];                    // N from weights

    int threads = 256;

    // Zero + L2-pin the grid (out_size = 256^3, divisible by 8).
    int n8 = out_size / 8;
    int zblocks = 148 * 4;
    forcegrid_zero_kernel<<<zblocks, threads, 0, 0>>>(grid, n8);

    // Persistent deposit with grid-stride double-buffer (best measured config).
    int blocks = 148 * 8;
    forcegrid_deposit_kernel<<<blocks, threads, 0, 0>>>(
        (const float4*)positions, (const float4*)weights,
        positions, weights, grid, n_particles);
}